// round 3
// baseline (speedup 1.0000x reference)
#include <cuda_runtime.h>
#include <cuda_bf16.h>
#include <math.h>

#define NN   100000
#define EE   1600000
#define FIN  165
#define HH   128
#define CCLS 2

// ---------------- static device scratch (no allocation allowed) ----------------
__device__ __align__(16) float g_deg [NN];
__device__ __align__(16) float g_dinv[NN];
__device__ __align__(16) float g_w   [EE];
__device__ __align__(16) int   g_src [EE];
__device__ __align__(16) int   g_dst [EE];

__device__ __align__(16) float g_A [NN * HH];   // x @ (W0 - W2)
__device__ __align__(16) float g_B [NN * HH];   // x @ W1   (later: B + 2T)
__device__ __align__(16) float g_C [NN * HH];   // x @ W2
__device__ __align__(16) float g_T [NN * HH];   // P(C)
__device__ __align__(16) float g_U [NN * HH];   // P(B + 2T)
__device__ __align__(16) float g_Hb[NN * HH];   // layer-1 activation h

__device__ __align__(16) float g_Wcat1[FIN * 3 * HH];  // 165 x 384
__device__ __align__(16) float g_Wcat2[HH  * 3 * HH];  // 128 x 384

// ---------------- small utility kernels ----------------
__global__ void k_zero(float* __restrict__ p, int n4) {
    int i = blockIdx.x * blockDim.x + threadIdx.x;
    if (i < n4) ((float4*)p)[i] = make_float4(0.f, 0.f, 0.f, 0.f);
}

// edge_index is int32 (JAX x64 disabled canonicalizes int64 -> int32).
// Defensive clamp: out-of-range indices become degenerate self-loops (w=0, skipped),
// so a dtype mistake shows up as rel_err, not an address-space trap.
__global__ void k_deg(const int* __restrict__ ei) {
    int e = blockIdx.x * blockDim.x + threadIdx.x;
    if (e >= EE) return;
    int s = ei[e];
    int d = ei[EE + e];
    if ((unsigned)s >= NN || (unsigned)d >= NN) { s = 0; d = 0; }
    g_src[e] = s;
    g_dst[e] = d;
    if (s != d) atomicAdd(&g_deg[s], 1.0f);
}

__global__ void k_dinv() {
    int i = blockIdx.x * blockDim.x + threadIdx.x;
    if (i >= NN) return;
    float d = g_deg[i];
    g_dinv[i] = (d > 0.f) ? rsqrtf(d) : 0.f;
}

__global__ void k_edgew() {
    int e = blockIdx.x * blockDim.x + threadIdx.x;
    if (e >= EE) return;
    int s = g_src[e], d = g_dst[e];
    g_w[e] = (s != d) ? (-g_dinv[s] * g_dinv[d]) : 0.f;
}

// Build Wcat = [W0 - W2 | W1 | W2], shape K x 384 (K-major rows)
__global__ void k_wcat(const float* __restrict__ W, float* __restrict__ Wcat, int kdim) {
    int idx = blockIdx.x * blockDim.x + threadIdx.x;
    int tot = kdim * 3 * HH;
    if (idx >= tot) return;
    int f = idx / (3 * HH);
    int c = idx - f * (3 * HH);
    float v;
    if (c < HH)            v = W[f * HH + c] - W[2 * kdim * HH + f * HH + c];
    else if (c < 2 * HH)   v = W[kdim * HH + f * HH + (c - HH)];
    else                   v = W[2 * kdim * HH + f * HH + (c - 2 * HH)];
    Wcat[idx] = v;
}

// ---------------- GEMM: out[N x 384] = X[N x K] @ W[K x 384], split into 3 buffers ----------------
__global__ void k_gemm384(const float* __restrict__ X, const float* __restrict__ W,
                          float* __restrict__ o0, float* __restrict__ o1, float* __restrict__ o2,
                          int n, int k) {
    __shared__ float Xs[16][65];
    __shared__ float Ws[16][64];

    int tid  = threadIdx.x;           // 256 threads
    int tx   = tid & 15;
    int ty   = tid >> 4;
    int n0   = blockIdx.x * 64;       // 0..320
    int row0 = blockIdx.y * 64;

    float acc[4][4];
#pragma unroll
    for (int i = 0; i < 4; i++)
#pragma unroll
        for (int j = 0; j < 4; j++) acc[i][j] = 0.f;

    for (int k0 = 0; k0 < k; k0 += 16) {
#pragma unroll
        for (int i = 0; i < 4; i++) {
            int li = tid + 256 * i;
            int kk = li & 15;
            int m  = li >> 4;
            int gr = row0 + m, gk = k0 + kk;
            Xs[kk][m] = (gr < n && gk < k) ? X[(size_t)gr * k + gk] : 0.f;
        }
#pragma unroll
        for (int i = 0; i < 4; i++) {
            int li = tid + 256 * i;
            int nn = li & 63;
            int kk = li >> 6;
            int gk = k0 + kk;
            Ws[kk][nn] = (gk < k) ? W[(size_t)gk * 384 + n0 + nn] : 0.f;
        }
        __syncthreads();
#pragma unroll
        for (int kk = 0; kk < 16; kk++) {
            float a0 = Xs[kk][ty * 4 + 0], a1 = Xs[kk][ty * 4 + 1];
            float a2 = Xs[kk][ty * 4 + 2], a3 = Xs[kk][ty * 4 + 3];
            float b0 = Ws[kk][tx * 4 + 0], b1 = Ws[kk][tx * 4 + 1];
            float b2 = Ws[kk][tx * 4 + 2], b3 = Ws[kk][tx * 4 + 3];
            acc[0][0] += a0 * b0; acc[0][1] += a0 * b1; acc[0][2] += a0 * b2; acc[0][3] += a0 * b3;
            acc[1][0] += a1 * b0; acc[1][1] += a1 * b1; acc[1][2] += a1 * b2; acc[1][3] += a1 * b3;
            acc[2][0] += a2 * b0; acc[2][1] += a2 * b1; acc[2][2] += a2 * b2; acc[2][3] += a2 * b3;
            acc[3][0] += a3 * b0; acc[3][1] += a3 * b1; acc[3][2] += a3 * b2; acc[3][3] += a3 * b3;
        }
        __syncthreads();
    }

    float* O = (n0 < 128) ? o0 : ((n0 < 256) ? o1 : o2);
    int cb = (n0 & 127) + tx * 4;
#pragma unroll
    for (int i = 0; i < 4; i++) {
        int gr = row0 + ty * 4 + i;
        if (gr < n) {
#pragma unroll
            for (int j = 0; j < 4; j++)
                O[(size_t)gr * HH + cb + j] = acc[i][j];
        }
    }
}

// ---------------- sparse propagation: Y[dst] += w * X[src], one warp per edge ----------------
__global__ void k_prop(const float* __restrict__ X, float* __restrict__ Y) {
    int e = blockIdx.x * (blockDim.x >> 5) + (threadIdx.x >> 5);
    if (e >= EE) return;
    float wt = g_w[e];
    if (wt == 0.f) return;
    int lane = threadIdx.x & 31;
    const float4* xs = (const float4*)(X + (size_t)g_src[e] * HH);
    float4 v = xs[lane];
    v.x *= wt; v.y *= wt; v.z *= wt; v.w *= wt;
    float* yd = Y + (size_t)g_dst[e] * HH + lane * 4;
    asm volatile("red.global.add.v4.f32 [%0], {%1,%2,%3,%4};"
                 :: "l"(yd), "f"(v.x), "f"(v.y), "f"(v.z), "f"(v.w) : "memory");
}

// B = B + 2*T  (elementwise, float4)
__global__ void k_axpy2(float* __restrict__ B, const float* __restrict__ T, int n4) {
    int i = blockIdx.x * blockDim.x + threadIdx.x;
    if (i >= n4) return;
    float4 b = ((float4*)B)[i];
    float4 t = ((const float4*)T)[i];
    b.x += 2.f * t.x; b.y += 2.f * t.y; b.z += 2.f * t.z; b.w += 2.f * t.w;
    ((float4*)B)[i] = b;
}

// Hb = relu(A + U + b1)
__global__ void k_relu_combine(const float* __restrict__ A, const float* __restrict__ U,
                               const float* __restrict__ b1, float* __restrict__ Hb, int n4) {
    int i = blockIdx.x * blockDim.x + threadIdx.x;
    if (i >= n4) return;
    int cb = (i & 31) * 4;  // column base within the 128-wide row
    float4 a = ((const float4*)A)[i];
    float4 u = ((const float4*)U)[i];
    a.x = fmaxf(a.x + u.x + b1[cb + 0], 0.f);
    a.y = fmaxf(a.y + u.y + b1[cb + 1], 0.f);
    a.z = fmaxf(a.z + u.z + b1[cb + 2], 0.f);
    a.w = fmaxf(a.w + u.w + b1[cb + 3], 0.f);
    ((float4*)Hb)[i] = a;
}

// final: h2 = Hb + A2 + U + b2 ; z = h2 @ Wl + bl ; log_softmax -> out. One warp per node.
__global__ void k_final(const float* __restrict__ Hb, const float* __restrict__ A2,
                        const float* __restrict__ U, const float* __restrict__ b2,
                        const float* __restrict__ Wl, const float* __restrict__ bl,
                        float* __restrict__ out) {
    int node = blockIdx.x * (blockDim.x >> 5) + (threadIdx.x >> 5);
    if (node >= NN) return;
    int lane = threadIdx.x & 31;
    size_t base = (size_t)node * 32 + lane;
    float4 h = ((const float4*)Hb)[base];
    float4 a = ((const float4*)A2)[base];
    float4 u = ((const float4*)U)[base];
    int cb = lane * 4;
    float h0 = h.x + a.x + u.x + b2[cb + 0];
    float h1 = h.y + a.y + u.y + b2[cb + 1];
    float h2v = h.z + a.z + u.z + b2[cb + 2];
    float h3 = h.w + a.w + u.w + b2[cb + 3];
    float z0 = h0 * Wl[(cb + 0) * 2 + 0] + h1 * Wl[(cb + 1) * 2 + 0]
             + h2v * Wl[(cb + 2) * 2 + 0] + h3 * Wl[(cb + 3) * 2 + 0];
    float z1 = h0 * Wl[(cb + 0) * 2 + 1] + h1 * Wl[(cb + 1) * 2 + 1]
             + h2v * Wl[(cb + 2) * 2 + 1] + h3 * Wl[(cb + 3) * 2 + 1];
#pragma unroll
    for (int o = 16; o > 0; o >>= 1) {
        z0 += __shfl_xor_sync(0xffffffffu, z0, o);
        z1 += __shfl_xor_sync(0xffffffffu, z1, o);
    }
    if (lane == 0) {
        z0 += bl[0]; z1 += bl[1];
        float m  = fmaxf(z0, z1);
        float ls = logf(expf(z0 - m) + expf(z1 - m));
        out[(size_t)node * 2 + 0] = z0 - m - ls;
        out[(size_t)node * 2 + 1] = z1 - m - ls;
    }
}

// tail of d_out: edge_index passed through (int32 values, exact in fp32 for N<2^24)
__global__ void k_tail(const int* __restrict__ ei, float* __restrict__ out, int tail) {
    int i = blockIdx.x * blockDim.x + threadIdx.x;
    if (i >= tail) return;
    out[NN * CCLS + i] = (i < 2 * EE) ? (float)ei[i] : 0.f;
}

// ---------------- launch ----------------
extern "C" void kernel_launch(void* const* d_in, const int* in_sizes, int n_in,
                              void* d_out, int out_size) {
    const float* x  = (const float*)d_in[0];
    const int*   ei = (const int*)d_in[1];      // int32 edge_index (JAX x64 off)
    const float* W1 = (const float*)d_in[2];
    const float* b1 = (const float*)d_in[3];
    const float* W2 = (const float*)d_in[4];
    const float* b2 = (const float*)d_in[5];
    const float* Wl = (const float*)d_in[6];
    const float* bl = (const float*)d_in[7];
    float* out = (float*)d_out;

    float *dDeg, *dA, *dB, *dC, *dT, *dU, *dHb, *dWc1, *dWc2;
    cudaGetSymbolAddress((void**)&dDeg, g_deg);
    cudaGetSymbolAddress((void**)&dA,   g_A);
    cudaGetSymbolAddress((void**)&dB,   g_B);
    cudaGetSymbolAddress((void**)&dC,   g_C);
    cudaGetSymbolAddress((void**)&dT,   g_T);
    cudaGetSymbolAddress((void**)&dU,   g_U);
    cudaGetSymbolAddress((void**)&dHb,  g_Hb);
    cudaGetSymbolAddress((void**)&dWc1, g_Wcat1);
    cudaGetSymbolAddress((void**)&dWc2, g_Wcat2);

    const int NH4 = NN * HH / 4;
    const int ZB  = 256;

    // edge normalization weights
    k_zero<<<(NN / 4 + ZB - 1) / ZB, ZB>>>(dDeg, NN / 4);
    k_deg<<<(EE + 255) / 256, 256>>>(ei);
    k_dinv<<<(NN + 255) / 256, 256>>>();
    k_edgew<<<(EE + 255) / 256, 256>>>();

    // layer 1: A,B,C = x @ [W0-W2 | W1 | W2]
    k_wcat<<<(FIN * 384 + 255) / 256, 256>>>(W1, dWc1, FIN);
    {
        dim3 g(6, (NN + 63) / 64);
        k_gemm384<<<g, 256>>>(x, dWc1, dA, dB, dC, NN, FIN);
    }
    k_zero<<<(NH4 + ZB - 1) / ZB, ZB>>>(dT, NH4);
    k_prop<<<(EE * 32 + 255) / 256, 256>>>(dC, dT);
    k_axpy2<<<(NH4 + ZB - 1) / ZB, ZB>>>(dB, dT, NH4);
    k_zero<<<(NH4 + ZB - 1) / ZB, ZB>>>(dU, NH4);
    k_prop<<<(EE * 32 + 255) / 256, 256>>>(dB, dU);
    k_relu_combine<<<(NH4 + ZB - 1) / ZB, ZB>>>(dA, dU, b1, dHb, NH4);

    // layer 2: A,B,C = h @ [W0-W2 | W1 | W2]
    k_wcat<<<(HH * 384 + 255) / 256, 256>>>(W2, dWc2, HH);
    {
        dim3 g(6, (NN + 63) / 64);
        k_gemm384<<<g, 256>>>(dHb, dWc2, dA, dB, dC, NN, HH);
    }
    k_zero<<<(NH4 + ZB - 1) / ZB, ZB>>>(dT, NH4);
    k_prop<<<(EE * 32 + 255) / 256, 256>>>(dC, dT);
    k_axpy2<<<(NH4 + ZB - 1) / ZB, ZB>>>(dB, dT, NH4);
    k_zero<<<(NH4 + ZB - 1) / ZB, ZB>>>(dU, NH4);
    k_prop<<<(EE * 32 + 255) / 256, 256>>>(dB, dU);

    // final: residual + linear + log_softmax
    k_final<<<(NN * 32 + 255) / 256, 256>>>(dHb, dA, dU, b2, Wl, bl, out);

    int tail = out_size - NN * CCLS;
    if (tail > 0)
        k_tail<<<(tail + 255) / 256, 256>>>(ei, out, tail);
}

// round 4
// speedup vs baseline: 1.5216x; 1.5216x over previous
#include <cuda_runtime.h>
#include <cuda_bf16.h>
#include <math.h>

#define NN    100000
#define EE    1600000
#define FIN   165
#define HH    128
#define CCLS  2
#define CHUNK 512
#define NB    ((NN + CHUNK - 1) / CHUNK)   // 196

// ---------------- static device scratch (no allocation allowed) ----------------
__device__ __align__(16) float g_deg [NN];
__device__ __align__(16) float g_dinv[NN];
__device__ __align__(16) float g_w   [EE];
__device__ __align__(16) int   g_src [EE];
__device__ __align__(16) int   g_dst [EE];

// CSR (sorted by dst)
__device__ __align__(16) int   g_cnt [NN];
__device__ __align__(16) int   g_tmp [NN];
__device__ __align__(16) int   g_ptr [NN + 1];
__device__ __align__(16) int   g_fill[NN];
__device__ __align__(16) int   g_bsum[NB];
__device__ __align__(16) int   g_boff[NB];
__device__ __align__(16) int   g_esrc[EE];
__device__ __align__(16) float g_ews [EE];

__device__ __align__(16) float g_A [NN * HH];   // x @ (W0 - W2)
__device__ __align__(16) float g_B [NN * HH];   // x @ W1, then B + 2*P(C)
__device__ __align__(16) float g_C [NN * HH];   // x @ W2
__device__ __align__(16) float g_Hb[NN * HH];   // layer-1 activation h

__device__ __align__(16) float g_Wcat1[FIN * 3 * HH];  // 165 x 384
__device__ __align__(16) float g_Wcat2[HH  * 3 * HH];  // 128 x 384

// ---------------- setup kernels ----------------
__global__ void k_zero(float* __restrict__ p, int n4) {
    int i = blockIdx.x * blockDim.x + threadIdx.x;
    if (i < n4) ((float4*)p)[i] = make_float4(0.f, 0.f, 0.f, 0.f);
}

// edge_index is int32. Clamp defensively (degenerates to self-loop -> w=0 -> skipped).
__global__ void k_deg(const int* __restrict__ ei) {
    int e = blockIdx.x * blockDim.x + threadIdx.x;
    if (e >= EE) return;
    int s = ei[e];
    int d = ei[EE + e];
    if ((unsigned)s >= NN || (unsigned)d >= NN) { s = 0; d = 0; }
    g_src[e] = s;
    g_dst[e] = d;
    if (s != d) atomicAdd(&g_deg[s], 1.0f);
}

__global__ void k_dinv() {
    int i = blockIdx.x * blockDim.x + threadIdx.x;
    if (i >= NN) return;
    float d = g_deg[i];
    g_dinv[i] = (d > 0.f) ? rsqrtf(d) : 0.f;
}

// edge weight + in-degree histogram of edges that actually carry weight
__global__ void k_edgew() {
    int e = blockIdx.x * blockDim.x + threadIdx.x;
    if (e >= EE) return;
    int s = g_src[e], d = g_dst[e];
    float w = (s != d) ? (-g_dinv[s] * g_dinv[d]) : 0.f;
    g_w[e] = w;
    if (w != 0.f) atomicAdd(&g_cnt[d], 1);
}

// ---------------- 3-kernel exclusive scan of g_cnt -> g_ptr / g_fill ----------------
__global__ void k_scanA() {                 // <<<NB, CHUNK>>>
    __shared__ int s[CHUNK];
    int i = blockIdx.x * CHUNK + threadIdx.x;
    int v = (i < NN) ? g_cnt[i] : 0;
    s[threadIdx.x] = v;
    __syncthreads();
    for (int off = 1; off < CHUNK; off <<= 1) {
        int t = (threadIdx.x >= off) ? s[threadIdx.x - off] : 0;
        __syncthreads();
        s[threadIdx.x] += t;
        __syncthreads();
    }
    if (i < NN) g_tmp[i] = s[threadIdx.x];
    if (threadIdx.x == CHUNK - 1) g_bsum[blockIdx.x] = s[CHUNK - 1];
}

__global__ void k_scanB() {                 // <<<1, 256>>>
    __shared__ int s[256];
    int v = (threadIdx.x < NB) ? g_bsum[threadIdx.x] : 0;
    s[threadIdx.x] = v;
    __syncthreads();
    for (int off = 1; off < 256; off <<= 1) {
        int t = (threadIdx.x >= off) ? s[threadIdx.x - off] : 0;
        __syncthreads();
        s[threadIdx.x] += t;
        __syncthreads();
    }
    if (threadIdx.x < NB) g_boff[threadIdx.x] = s[threadIdx.x] - v;   // exclusive
    if (threadIdx.x == NB - 1) g_ptr[NN] = s[threadIdx.x];            // total
}

__global__ void k_scanC() {                 // <<<NB, CHUNK>>>
    int i = blockIdx.x * CHUNK + threadIdx.x;
    if (i >= NN) return;
    int excl = g_boff[blockIdx.x] + g_tmp[i] - g_cnt[i];
    g_ptr[i]  = excl;
    g_fill[i] = excl;
}

__global__ void k_scatter() {
    int e = blockIdx.x * blockDim.x + threadIdx.x;
    if (e >= EE) return;
    float w = g_w[e];
    if (w == 0.f) return;
    int pos = atomicAdd(&g_fill[g_dst[e]], 1);
    g_esrc[pos] = g_src[e];
    g_ews[pos]  = w;
}

// ---------------- Wcat = [W0 - W2 | W1 | W2], K x 384 ----------------
__global__ void k_wcat(const float* __restrict__ W, float* __restrict__ Wcat, int kdim) {
    int idx = blockIdx.x * blockDim.x + threadIdx.x;
    int tot = kdim * 3 * HH;
    if (idx >= tot) return;
    int f = idx / (3 * HH);
    int c = idx - f * (3 * HH);
    float v;
    if (c < HH)            v = W[f * HH + c] - W[2 * kdim * HH + f * HH + c];
    else if (c < 2 * HH)   v = W[kdim * HH + f * HH + (c - HH)];
    else                   v = W[2 * kdim * HH + f * HH + (c - 2 * HH)];
    Wcat[idx] = v;
}

// ---------------- GEMM: 128x128 tile, 8x8 micro, out split to 3 buffers ----------------
__global__ void __launch_bounds__(256) k_gemm(
        const float* __restrict__ X, const float* __restrict__ W,
        float* __restrict__ o0, float* __restrict__ o1, float* __restrict__ o2,
        int n, int k) {
    __shared__ float Xs[8][136];   // row stride 544B (16B-aligned)
    __shared__ float Ws[8][128];

    int tid  = threadIdx.x;
    int tx   = tid & 15;           // N dir (16 x 8 = 128)
    int ty   = tid >> 4;           // M dir (16 x 8 = 128)
    int row0 = blockIdx.y * 128;
    int n0   = blockIdx.x * 128;

    float acc[8][8];
#pragma unroll
    for (int i = 0; i < 8; i++)
#pragma unroll
        for (int j = 0; j < 8; j++) acc[i][j] = 0.f;

    for (int k0 = 0; k0 < k; k0 += 8) {
#pragma unroll
        for (int i = 0; i < 4; i++) {           // X tile: 128 x 8, transposed store
            int li = tid + 256 * i;
            int m  = li >> 3;
            int kk = li & 7;
            int gr = row0 + m, gk = k0 + kk;
            Xs[kk][m] = (gr < n && gk < k) ? X[(size_t)gr * k + gk] : 0.f;
        }
#pragma unroll
        for (int i = 0; i < 4; i++) {           // W tile: 8 x 128, coalesced
            int li = tid + 256 * i;
            int kk = li >> 7;
            int nn = li & 127;
            int gk = k0 + kk;
            Ws[kk][nn] = (gk < k) ? W[(size_t)gk * 384 + n0 + nn] : 0.f;
        }
        __syncthreads();
#pragma unroll
        for (int kk = 0; kk < 8; kk++) {
            float a[8], b[8];
            *(float4*)&a[0] = *(const float4*)&Xs[kk][ty * 8];
            *(float4*)&a[4] = *(const float4*)&Xs[kk][ty * 8 + 4];
            *(float4*)&b[0] = *(const float4*)&Ws[kk][tx * 8];
            *(float4*)&b[4] = *(const float4*)&Ws[kk][tx * 8 + 4];
#pragma unroll
            for (int i = 0; i < 8; i++)
#pragma unroll
                for (int j = 0; j < 8; j++) acc[i][j] += a[i] * b[j];
        }
        __syncthreads();
    }

    float* O = (blockIdx.x == 0) ? o0 : ((blockIdx.x == 1) ? o1 : o2);
#pragma unroll
    for (int i = 0; i < 8; i++) {
        int gr = row0 + ty * 8 + i;
        if (gr < n) {
            float4 v0 = make_float4(acc[i][0], acc[i][1], acc[i][2], acc[i][3]);
            float4 v1 = make_float4(acc[i][4], acc[i][5], acc[i][6], acc[i][7]);
            *(float4*)(O + (size_t)gr * HH + tx * 8)     = v0;
            *(float4*)(O + (size_t)gr * HH + tx * 8 + 4) = v1;
        }
    }
}

// ---------------- CSR prop, one warp per node, fused epilogues ----------------
// MODE 1: Y[node] = P0[node] + 2*acc            (B += 2*P(C))
// MODE 2: Y[node] = relu(P0[node] + acc + bias) (Hb)
// MODE 3: h = P0 + P1 + acc + bias; z = h@Wl + bl; log_softmax -> Y (2 floats/node)
template <int MODE>
__global__ void __launch_bounds__(256) k_prop_csr(
        const float* __restrict__ X,
        const float* __restrict__ P0, const float* __restrict__ P1,
        const float* __restrict__ bias,
        const float* __restrict__ Wl, const float* __restrict__ bl,
        float* __restrict__ Y) {
    int node = blockIdx.x * 8 + (threadIdx.x >> 5);
    if (node >= NN) return;
    int lane = threadIdx.x & 31;
    int beg = g_ptr[node], end = g_ptr[node + 1];

    float4 acc = make_float4(0.f, 0.f, 0.f, 0.f);
#pragma unroll 4
    for (int i = beg; i < end; i++) {
        int   s  = g_esrc[i];
        float wt = g_ews[i];
        float4 v = *(const float4*)(X + (size_t)s * HH + lane * 4);
        acc.x += wt * v.x; acc.y += wt * v.y;
        acc.z += wt * v.z; acc.w += wt * v.w;
    }

    size_t o  = (size_t)node * 32 + lane;
    int    cb = lane * 4;

    if (MODE == 1) {
        float4 b = ((const float4*)P0)[o];
        b.x += 2.f * acc.x; b.y += 2.f * acc.y;
        b.z += 2.f * acc.z; b.w += 2.f * acc.w;
        ((float4*)Y)[o] = b;
    } else if (MODE == 2) {
        float4 a = ((const float4*)P0)[o];
        a.x = fmaxf(a.x + acc.x + bias[cb + 0], 0.f);
        a.y = fmaxf(a.y + acc.y + bias[cb + 1], 0.f);
        a.z = fmaxf(a.z + acc.z + bias[cb + 2], 0.f);
        a.w = fmaxf(a.w + acc.w + bias[cb + 3], 0.f);
        ((float4*)Y)[o] = a;
    } else {
        float4 h = ((const float4*)P0)[o];
        float4 a = ((const float4*)P1)[o];
        float h0 = h.x + a.x + acc.x + bias[cb + 0];
        float h1 = h.y + a.y + acc.y + bias[cb + 1];
        float h2 = h.z + a.z + acc.z + bias[cb + 2];
        float h3 = h.w + a.w + acc.w + bias[cb + 3];
        float z0 = h0 * Wl[(cb + 0) * 2 + 0] + h1 * Wl[(cb + 1) * 2 + 0]
                 + h2 * Wl[(cb + 2) * 2 + 0] + h3 * Wl[(cb + 3) * 2 + 0];
        float z1 = h0 * Wl[(cb + 0) * 2 + 1] + h1 * Wl[(cb + 1) * 2 + 1]
                 + h2 * Wl[(cb + 2) * 2 + 1] + h3 * Wl[(cb + 3) * 2 + 1];
#pragma unroll
        for (int off = 16; off > 0; off >>= 1) {
            z0 += __shfl_xor_sync(0xffffffffu, z0, off);
            z1 += __shfl_xor_sync(0xffffffffu, z1, off);
        }
        if (lane == 0) {
            z0 += bl[0]; z1 += bl[1];
            float m  = fmaxf(z0, z1);
            float ls = logf(expf(z0 - m) + expf(z1 - m));
            Y[(size_t)node * 2 + 0] = z0 - m - ls;
            Y[(size_t)node * 2 + 1] = z1 - m - ls;
        }
    }
}

// tail of d_out: edge_index passed through
__global__ void k_tail(const int* __restrict__ ei, float* __restrict__ out, int tail) {
    int i = blockIdx.x * blockDim.x + threadIdx.x;
    if (i >= tail) return;
    out[NN * CCLS + i] = (i < 2 * EE) ? (float)ei[i] : 0.f;
}

// ---------------- launch ----------------
extern "C" void kernel_launch(void* const* d_in, const int* in_sizes, int n_in,
                              void* d_out, int out_size) {
    const float* x  = (const float*)d_in[0];
    const int*   ei = (const int*)d_in[1];
    const float* W1 = (const float*)d_in[2];
    const float* b1 = (const float*)d_in[3];
    const float* W2 = (const float*)d_in[4];
    const float* b2 = (const float*)d_in[5];
    const float* Wl = (const float*)d_in[6];
    const float* bl = (const float*)d_in[7];
    float* out = (float*)d_out;

    float *dDeg, *dA, *dB, *dC, *dHb, *dWc1, *dWc2;
    int   *dCnt;
    cudaGetSymbolAddress((void**)&dDeg, g_deg);
    cudaGetSymbolAddress((void**)&dCnt, g_cnt);
    cudaGetSymbolAddress((void**)&dA,   g_A);
    cudaGetSymbolAddress((void**)&dB,   g_B);
    cudaGetSymbolAddress((void**)&dC,   g_C);
    cudaGetSymbolAddress((void**)&dHb,  g_Hb);
    cudaGetSymbolAddress((void**)&dWc1, g_Wcat1);
    cudaGetSymbolAddress((void**)&dWc2, g_Wcat2);

    // ---- CSR build ----
    k_zero<<<(NN / 4 + 255) / 256, 256>>>(dDeg, NN / 4);
    k_zero<<<(NN / 4 + 255) / 256, 256>>>((float*)dCnt, NN / 4);
    k_deg<<<(EE + 255) / 256, 256>>>(ei);
    k_dinv<<<(NN + 255) / 256, 256>>>();
    k_edgew<<<(EE + 255) / 256, 256>>>();
    k_scanA<<<NB, CHUNK>>>();
    k_scanB<<<1, 256>>>();
    k_scanC<<<NB, CHUNK>>>();
    k_scatter<<<(EE + 255) / 256, 256>>>();

    const int PG = (NN + 7) / 8;    // prop grid (8 warps/block)

    // ---- layer 1 ----
    k_wcat<<<(FIN * 384 + 255) / 256, 256>>>(W1, dWc1, FIN);
    {
        dim3 g(3, (NN + 127) / 128);
        k_gemm<<<g, 256>>>(x, dWc1, dA, dB, dC, NN, FIN);
    }
    k_prop_csr<1><<<PG, 256>>>(dC, dB, nullptr, nullptr, nullptr, nullptr, dB);
    k_prop_csr<2><<<PG, 256>>>(dB, dA, nullptr, b1, nullptr, nullptr, dHb);

    // ---- layer 2 ----
    k_wcat<<<(HH * 384 + 255) / 256, 256>>>(W2, dWc2, HH);
    {
        dim3 g(3, (NN + 127) / 128);
        k_gemm<<<g, 256>>>(dHb, dWc2, dA, dB, dC, NN, HH);
    }
    k_prop_csr<1><<<PG, 256>>>(dC, dB, nullptr, nullptr, nullptr, nullptr, dB);
    k_prop_csr<3><<<PG, 256>>>(dB, dHb, dA, b2, Wl, bl, out);

    // ---- tail ----
    int tail = out_size - NN * CCLS;
    if (tail > 0)
        k_tail<<<(tail + 255) / 256, 256>>>(ei, out, tail);
}